// round 8
// baseline (speedup 1.0000x reference)
#include <cuda_runtime.h>
#include <cuda_fp16.h>
#include <cstdint>

#define NN 16384
#define DD 64
#define KK 128           // virtual K: [ah|al] . [w|w] (fp16 split; B stored once, K=64)
#define SROWA 256        // A smem row stride bytes (16 x 16B chunks)
#define SROWBB 128       // B smem row stride bytes (8 x 16B chunks)

constexpr float TAU_F   = 0.28f;
constexpr float EPS_F   = 1e-8f;
constexpr float LOG2E_F = 1.4426950408889634f;

// Scratch (allocation-free: __device__ globals)
__device__ __half g_a[NN * KK];               // A rows: [ah | al], scaled by log2e/TAU
__device__ __half g_b[NN * DD];               // B rows: w fp16 (K=64, used for both halves)
__device__ float g_pos[NN];
__device__ float g_partial[(NN / 128) * NN];  // per-column-block partial row sums
__device__ float g_blocksum[64];

__device__ __forceinline__ uint32_t smem_u32(const void* p) {
    uint32_t a;
    asm("{ .reg .u64 t; cvta.to.shared.u64 t, %1; cvt.u32.u64 %0, t; }" : "=r"(a) : "l"(p));
    return a;
}
__device__ __forceinline__ void cp16(uint32_t saddr, const void* g) {
    asm volatile("cp.async.cg.shared.global [%0], [%1], 16;" :: "r"(saddr), "l"(g));
}
__device__ __forceinline__ void ldsm_x4(uint32_t* r, uint32_t addr) {
    asm volatile("ldmatrix.sync.aligned.m8n8.x4.shared.b16 {%0,%1,%2,%3}, [%4];"
                 : "=r"(r[0]), "=r"(r[1]), "=r"(r[2]), "=r"(r[3]) : "r"(addr));
}
__device__ __forceinline__ void mma16816(float* c, const uint32_t* a,
                                         uint32_t b0, uint32_t b1) {
    asm volatile(
        "mma.sync.aligned.m16n8k16.row.col.f32.f16.f16.f32 "
        "{%0,%1,%2,%3}, {%4,%5,%6,%7}, {%8,%9}, {%0,%1,%2,%3};"
        : "+f"(c[0]), "+f"(c[1]), "+f"(c[2]), "+f"(c[3])
        : "r"(a[0]), "r"(a[1]), "r"(a[2]), "r"(a[3]), "r"(b0), "r"(b1));
}
__device__ __forceinline__ float ex2v(float x) {
    float e;
    asm volatile("ex2.approx.ftz.f32 %0, %1;" : "=f"(e) : "f"(x));
    return e;
}

// ---------------------------------------------------------------------------
// Kernel 1: normalize, fp16 hi/lo split for A, fp16 w for B.
// ---------------------------------------------------------------------------
__global__ void prep_kernel(const float* __restrict__ U, const float* __restrict__ I) {
    int row  = blockIdx.x * 8 + (threadIdx.x >> 5);
    int lane = threadIdx.x & 31;

    const float* up = U + (size_t)row * DD;
    const float* ip = I + (size_t)row * DD;
    float u0 = up[lane], u1 = up[lane + 32];
    float i0 = ip[lane], i1 = ip[lane + 32];

    float su = u0 * u0 + u1 * u1;
    float si = i0 * i0 + i1 * i1;
#pragma unroll
    for (int o = 16; o; o >>= 1) {
        su += __shfl_xor_sync(0xffffffffu, su, o);
        si += __shfl_xor_sync(0xffffffffu, si, o);
    }
    float inu = rsqrtf(fmaxf(su, 1e-24f));
    float ini = rsqrtf(fmaxf(si, 1e-24f));

    float un0 = u0 * inu, un1 = u1 * inu;
    float vn0 = i0 * ini, vn1 = i1 * ini;

    float d = un0 * vn0 + un1 * vn1;
#pragma unroll
    for (int o = 16; o; o >>= 1) d += __shfl_xor_sync(0xffffffffu, d, o);

    const float SC = LOG2E_F / TAU_F;   // GEMM output directly = log2 of each exp term
    float a0 = un0 * SC, a1 = un1 * SC;
    float w0 = un0 + vn0, w1 = un1 + vn1;

    __half ah0 = __float2half_rn(a0);
    __half ah1 = __float2half_rn(a1);
    __half al0 = __float2half_rn(a0 - __half2float(ah0));
    __half al1 = __float2half_rn(a1 - __half2float(ah1));

    size_t abase = (size_t)row * KK;
    g_a[abase +  0 + lane] = ah0;  g_a[abase + 32 + lane] = ah1;
    g_a[abase + 64 + lane] = al0;  g_a[abase + 96 + lane] = al1;

    size_t bbase = (size_t)row * DD;
    g_b[bbase + lane]      = __float2half_rn(w0);
    g_b[bbase + 32 + lane] = __float2half_rn(w1);

    if (lane == 0) g_pos[row] = d * (1.0f / TAU_F);
}

// ---------------------------------------------------------------------------
// Kernel 2: fp16 mma.sync GEMM, 128x128 tile, two 16-col N-passes per warp;
// pass0's ex2/row-sum epilogue is interleaved into pass1's k-loop so MUFU
// overlaps the tensor pipe. 8 warps 2(M) x 4(N); warp tile 64x32.
// ---------------------------------------------------------------------------
__global__ void __launch_bounds__(256, 2) gemm_exp_kernel() {
    extern __shared__ __align__(16) char smem[];
    const uint32_t sb = smem_u32(smem);
    const uint32_t sA = sb;                    // 32 KB (128 rows x 256B)
    const uint32_t sB = sb + 128 * SROWA;      // 16 KB (128 rows x 128B)

    const int tid  = threadIdx.x;
    const int wid  = tid >> 5;
    const int lane = tid & 31;
    const int wm   = wid >> 2;                 // 0..1
    const int wn   = wid & 3;                  // 0..3
    const int bm = blockIdx.y, bn = blockIdx.x;

    const char* Ag = (const char*)g_a + (size_t)bm * 128 * (KK * 2);
    const char* Bg = (const char*)g_b + (size_t)bn * 128 * (DD * 2);

    // Stage 0: A chunks 0..7 (ah) + all of B.
#pragma unroll
    for (int it = 0; it < 4; it++) {
        int idx = it * 256 + tid;
        int row = idx >> 3;
        int c   = idx & 7;
        uint32_t sw = (uint32_t)((c ^ (row & 7)) << 4);
        cp16(sA + row * SROWA + sw, Ag + (size_t)row * (KK * 2) + c * 16);
        cp16(sB + row * SROWBB + sw, Bg + (size_t)row * (DD * 2) + c * 16);
    }
    asm volatile("cp.async.commit_group;" ::: "memory");

    // Stage 1: A chunks 8..15 (al).
#pragma unroll
    for (int it = 0; it < 4; it++) {
        int idx = it * 256 + tid;
        int row = idx >> 3;
        int c   = (idx & 7) + 8;
        uint32_t sw = (uint32_t)((c ^ (row & 7)) << 4);
        cp16(sA + row * SROWA + sw, Ag + (size_t)row * (KK * 2) + c * 16);
    }
    asm volatile("cp.async.commit_group;" ::: "memory");

    const int lr16 = lane & 15;
    const int lhi  = lane >> 4;
    const int arow = wm * 64 + lr16;           // + mf*16

    float acc0[4][2][4], acc1[4][2][4];
#pragma unroll
    for (int i = 0; i < 4; i++)
#pragma unroll
        for (int j = 0; j < 2; j++)
#pragma unroll
            for (int r = 0; r < 4; r++) { acc0[i][j][r] = 0.f; acc1[i][j][r] = 0.f; }

    float rs0[4] = {0.f, 0.f, 0.f, 0.f};       // row g sums per mf
    float rs1[4] = {0.f, 0.f, 0.f, 0.f};       // row g+8 sums per mf

    // ---------------- PASS 0: warp cols 0..15 (full K) ----------------
    const int brow0 = wn * 32 + lr16;          // pass 0 B rows
#pragma unroll
    for (int half = 0; half < 2; half++) {
        if (half == 0) asm volatile("cp.async.wait_group 1;" ::: "memory");
        else           asm volatile("cp.async.wait_group 0;" ::: "memory");
        __syncthreads();
#pragma unroll
        for (int ks = 0; ks < 4; ks++) {
            const int chb = 2 * ks + lhi;
            const int cha = half * 8 + chb;
            uint32_t a[4][4], b[4];
#pragma unroll
            for (int mf = 0; mf < 4; mf++) {
                int row = arow + mf * 16;
                ldsm_x4(a[mf], sA + row * SROWA + ((cha ^ (row & 7)) << 4));
            }
            ldsm_x4(b, sB + brow0 * SROWBB + ((chb ^ (brow0 & 7)) << 4));
#pragma unroll
            for (int mf = 0; mf < 4; mf++) {
                mma16816(acc0[mf][0], a[mf], b[0], b[2]);
                mma16816(acc0[mf][1], a[mf], b[1], b[3]);
            }
        }
    }

    // ------- PASS 1: warp cols 16..31, pass0 epilogue interleaved -------
    const int brow1 = wn * 32 + 16 + lr16;
#pragma unroll
    for (int half = 0; half < 2; half++) {
#pragma unroll
        for (int ks = 0; ks < 4; ks++) {
            const int chb = 2 * ks + lhi;
            const int cha = half * 8 + chb;
            uint32_t a[4][4], b[4];
#pragma unroll
            for (int mf = 0; mf < 4; mf++) {
                int row = arow + mf * 16;
                ldsm_x4(a[mf], sA + row * SROWA + ((cha ^ (row & 7)) << 4));
            }
            ldsm_x4(b, sB + brow1 * SROWBB + ((chb ^ (brow1 & 7)) << 4));
#pragma unroll
            for (int mf = 0; mf < 4; mf++) {
                mma16816(acc1[mf][0], a[mf], b[0], b[2]);
                mma16816(acc1[mf][1], a[mf], b[1], b[3]);
            }
            // Interleaved epilogue slice of acc0: 4 ex2 per k-step.
            const int idx = half * 4 + ks;     // 0..7
            const int mf  = idx >> 1;
            const int nf  = idx & 1;
            rs0[mf] += ex2v(acc0[mf][nf][0]) + ex2v(acc0[mf][nf][1]);
            rs1[mf] += ex2v(acc0[mf][nf][2]) + ex2v(acc0[mf][nf][3]);
        }
    }

    // ---------------- Final epilogue: acc1 ----------------
#pragma unroll
    for (int mf = 0; mf < 4; mf++) {
#pragma unroll
        for (int nf = 0; nf < 2; nf++) {
            rs0[mf] += ex2v(acc1[mf][nf][0]) + ex2v(acc1[mf][nf][1]);
            rs1[mf] += ex2v(acc1[mf][nf][2]) + ex2v(acc1[mf][nf][3]);
        }
    }

    const int g  = lane >> 2;
    const int t4 = lane & 3;
#pragma unroll
    for (int mf = 0; mf < 4; mf++) {
        rs0[mf] += __shfl_xor_sync(0xffffffffu, rs0[mf], 1);
        rs0[mf] += __shfl_xor_sync(0xffffffffu, rs0[mf], 2);
        rs1[mf] += __shfl_xor_sync(0xffffffffu, rs1[mf], 1);
        rs1[mf] += __shfl_xor_sync(0xffffffffu, rs1[mf], 2);
    }

    __syncthreads();                           // tiles no longer needed; reuse smem
    float* red = (float*)smem;                 // [128 rows][4 wn]
    if (t4 == 0) {
#pragma unroll
        for (int mf = 0; mf < 4; mf++) {
            int r0 = wm * 64 + mf * 16 + g;
            red[r0 * 4 + wn]       = rs0[mf];
            red[(r0 + 8) * 4 + wn] = rs1[mf];
        }
    }
    __syncthreads();
    if (tid < 128) {
        float s = (red[tid * 4 + 0] + red[tid * 4 + 1]) +
                  (red[tid * 4 + 2] + red[tid * 4 + 3]);
        g_partial[(size_t)bn * NN + bm * 128 + tid] = s;   // fixed order, no atomics
    }
}

// ---------------------------------------------------------------------------
// Kernel 3: per-row total over 128 column-block partials, loss, block sums.
// ---------------------------------------------------------------------------
__global__ void reduce_kernel() {
    int r = blockIdx.x * blockDim.x + threadIdx.x;
    float t = 0.f;
#pragma unroll 8
    for (int cb = 0; cb < NN / 128; cb++) t += g_partial[(size_t)cb * NN + r];
    float lr = logf(t + EPS_F) - g_pos[r];

    __shared__ float sm[256];
    sm[threadIdx.x] = lr;
    __syncthreads();
    for (int o = 128; o; o >>= 1) {
        if (threadIdx.x < o) sm[threadIdx.x] += sm[threadIdx.x + o];
        __syncthreads();
    }
    if (threadIdx.x == 0) g_blocksum[blockIdx.x] = sm[0];
}

__global__ void final_kernel(float* __restrict__ out) {
    __shared__ float sm[64];
    int t = threadIdx.x;
    sm[t] = g_blocksum[t];
    __syncthreads();
    for (int o = 32; o; o >>= 1) {
        if (t < o) sm[t] += sm[t + o];
        __syncthreads();
    }
    if (t == 0) out[0] = sm[0] * (1.0f / (float)NN);
}

// ---------------------------------------------------------------------------
extern "C" void kernel_launch(void* const* d_in, const int* in_sizes, int n_in,
                              void* d_out, int out_size) {
    const float* U = (const float*)d_in[0];
    const float* I = (const float*)d_in[1];
    float* out = (float*)d_out;

    const int SMEM_BYTES = 128 * SROWA + 128 * SROWBB;   // 49152
    cudaFuncSetAttribute(gemm_exp_kernel,
                         cudaFuncAttributeMaxDynamicSharedMemorySize, SMEM_BYTES);

    prep_kernel<<<NN / 8, 256>>>(U, I);

    dim3 grid(NN / 128, NN / 128);
    gemm_exp_kernel<<<grid, 256, SMEM_BYTES>>>();

    reduce_kernel<<<NN / 256, 256>>>();
    final_kernel<<<1, 64>>>(out);
}

// round 9
// speedup vs baseline: 1.1266x; 1.1266x over previous
#include <cuda_runtime.h>
#include <cuda_fp16.h>
#include <cstdint>

#define NN 16384
#define DD 64
#define KK 128           // virtual K: [ah|al] . [w|w] (fp16 split; B stored once, K=64)
#define SROWA 256        // A smem row stride bytes (16 x 16B chunks)
#define SROWBB 128       // B smem row stride bytes (8 x 16B chunks)

constexpr float TAU_F   = 0.28f;
constexpr float EPS_F   = 1e-8f;
constexpr float LOG2E_F = 1.4426950408889634f;

// Scratch (allocation-free: __device__ globals)
__device__ __half g_a[NN * KK];               // A rows: [ah | al], scaled by log2e/TAU
__device__ __half g_b[NN * DD];               // B rows: w fp16 (K=64, used for both halves)
__device__ float g_pos[NN];
__device__ float g_partial[(NN / 128) * NN];  // per-column-block partial row sums
__device__ float g_blocksum[64];

__device__ __forceinline__ uint32_t smem_u32(const void* p) {
    uint32_t a;
    asm("{ .reg .u64 t; cvta.to.shared.u64 t, %1; cvt.u32.u64 %0, t; }" : "=r"(a) : "l"(p));
    return a;
}
__device__ __forceinline__ void cp16(uint32_t saddr, const void* g) {
    asm volatile("cp.async.cg.shared.global [%0], [%1], 16;" :: "r"(saddr), "l"(g));
}
__device__ __forceinline__ void ldsm_x4(uint32_t* r, uint32_t addr) {
    asm volatile("ldmatrix.sync.aligned.m8n8.x4.shared.b16 {%0,%1,%2,%3}, [%4];"
                 : "=r"(r[0]), "=r"(r[1]), "=r"(r[2]), "=r"(r[3]) : "r"(addr));
}
__device__ __forceinline__ void mma16816(float* c, const uint32_t* a,
                                         uint32_t b0, uint32_t b1) {
    asm volatile(
        "mma.sync.aligned.m16n8k16.row.col.f32.f16.f16.f32 "
        "{%0,%1,%2,%3}, {%4,%5,%6,%7}, {%8,%9}, {%0,%1,%2,%3};"
        : "+f"(c[0]), "+f"(c[1]), "+f"(c[2]), "+f"(c[3])
        : "r"(a[0]), "r"(a[1]), "r"(a[2]), "r"(a[3]), "r"(b0), "r"(b1));
}
__device__ __forceinline__ float ex2v(float x) {
    float e;
    asm volatile("ex2.approx.ftz.f32 %0, %1;" : "=f"(e) : "f"(x));
    return e;
}

// ---------------------------------------------------------------------------
// Kernel 1: normalize, fp16 hi/lo split for A, fp16 w for B.
// ---------------------------------------------------------------------------
__global__ void prep_kernel(const float* __restrict__ U, const float* __restrict__ I) {
    int row  = blockIdx.x * 8 + (threadIdx.x >> 5);
    int lane = threadIdx.x & 31;

    const float* up = U + (size_t)row * DD;
    const float* ip = I + (size_t)row * DD;
    float u0 = up[lane], u1 = up[lane + 32];
    float i0 = ip[lane], i1 = ip[lane + 32];

    float su = u0 * u0 + u1 * u1;
    float si = i0 * i0 + i1 * i1;
#pragma unroll
    for (int o = 16; o; o >>= 1) {
        su += __shfl_xor_sync(0xffffffffu, su, o);
        si += __shfl_xor_sync(0xffffffffu, si, o);
    }
    float inu = rsqrtf(fmaxf(su, 1e-24f));
    float ini = rsqrtf(fmaxf(si, 1e-24f));

    float un0 = u0 * inu, un1 = u1 * inu;
    float vn0 = i0 * ini, vn1 = i1 * ini;

    float d = un0 * vn0 + un1 * vn1;
#pragma unroll
    for (int o = 16; o; o >>= 1) d += __shfl_xor_sync(0xffffffffu, d, o);

    const float SC = LOG2E_F / TAU_F;   // GEMM output directly = log2 of each exp term
    float a0 = un0 * SC, a1 = un1 * SC;
    float w0 = un0 + vn0, w1 = un1 + vn1;

    __half ah0 = __float2half_rn(a0);
    __half ah1 = __float2half_rn(a1);
    __half al0 = __float2half_rn(a0 - __half2float(ah0));
    __half al1 = __float2half_rn(a1 - __half2float(ah1));

    size_t abase = (size_t)row * KK;
    g_a[abase +  0 + lane] = ah0;  g_a[abase + 32 + lane] = ah1;
    g_a[abase + 64 + lane] = al0;  g_a[abase + 96 + lane] = al1;

    size_t bbase = (size_t)row * DD;
    g_b[bbase + lane]      = __float2half_rn(w0);
    g_b[bbase + 32 + lane] = __float2half_rn(w1);

    if (lane == 0) g_pos[row] = d * (1.0f / TAU_F);
}

// ---------------------------------------------------------------------------
// Kernel 2: fp16 mma.sync GEMM, 128x128 tile. Warp tile 64x32 processed as
// four 16-row m-frag passes (k inner); pass mf's ex2 epilogue is interleaved
// into pass mf+1's MMA loop (ping-pong 16-reg acc buffers -> no spills).
// B fragments (K=64) loaded once into registers, reused by all passes.
// ---------------------------------------------------------------------------
__global__ void __launch_bounds__(256, 2) gemm_exp_kernel() {
    extern __shared__ __align__(16) char smem[];
    const uint32_t sb = smem_u32(smem);
    const uint32_t sA = sb;                    // 32 KB (128 rows x 256B)
    const uint32_t sB = sb + 128 * SROWA;      // 16 KB (128 rows x 128B)

    const int tid  = threadIdx.x;
    const int wid  = tid >> 5;
    const int lane = tid & 31;
    const int wm   = wid >> 2;                 // 0..1
    const int wn   = wid & 3;                  // 0..3
    const int bm = blockIdx.y, bn = blockIdx.x;

    const char* Ag = (const char*)g_a + (size_t)bm * 128 * (KK * 2);
    const char* Bg = (const char*)g_b + (size_t)bn * 128 * (DD * 2);

    // cp.async: A (16 chunks/row) + B (8 chunks/row).
#pragma unroll
    for (int it = 0; it < 8; it++) {
        int idx = it * 256 + tid;              // 0..2047
        int row = idx >> 4;
        int c   = idx & 15;
        uint32_t sw = (uint32_t)((c ^ (row & 7)) << 4);
        cp16(sA + row * SROWA + sw, Ag + (size_t)row * (KK * 2) + c * 16);
        if (c < 8)
            cp16(sB + row * SROWBB + sw, Bg + (size_t)row * (DD * 2) + c * 16);
    }
    asm volatile("cp.async.commit_group;" ::: "memory");
    asm volatile("cp.async.wait_group 0;" ::: "memory");
    __syncthreads();

    const int lr16 = lane & 15;
    const int lhi  = lane >> 4;

    // B fragments for all 4 k16-steps, kept in registers (reused by every pass).
    uint32_t bf[4][2][4];
#pragma unroll
    for (int ks = 0; ks < 4; ks++) {
        const int chb = 2 * ks + lhi;
#pragma unroll
        for (int p = 0; p < 2; p++) {
            int row = wn * 32 + p * 16 + lr16;
            ldsm_x4(bf[ks][p], sB + row * SROWBB + ((chb ^ (row & 7)) << 4));
        }
    }

    float acc[2][4][4];
    float rs0[4], rs1[4];
#pragma unroll
    for (int mf = 0; mf < 4; mf++) { rs0[mf] = 0.f; rs1[mf] = 0.f; }

#pragma unroll
    for (int mf = 0; mf < 4; mf++) {
        float (*C)[4] = acc[mf & 1];           // current pass accumulator
        float (*P)[4] = acc[(mf + 1) & 1];     // previous pass (being drained)
#pragma unroll
        for (int nf = 0; nf < 4; nf++)
#pragma unroll
            for (int r = 0; r < 4; r++) C[nf][r] = 0.f;

        const int arow = wm * 64 + mf * 16 + lr16;
        const uint32_t aBase = sA + arow * SROWA;
        const int asw = arow & 7;

#pragma unroll
        for (int it = 0; it < 8; it++) {       // half = it>>2, ks = it&3
            const int half = it >> 2;
            const int ks   = it & 3;
            const int cha  = half * 8 + 2 * ks + lhi;
            uint32_t a[4];
            ldsm_x4(a, aBase + ((cha ^ asw) << 4));
            mma16816(C[0], a, bf[ks][0][0], bf[ks][0][2]);
            mma16816(C[1], a, bf[ks][0][1], bf[ks][0][3]);
            mma16816(C[2], a, bf[ks][1][0], bf[ks][1][2]);
            mma16816(C[3], a, bf[ks][1][1], bf[ks][1][3]);
            if (mf > 0) {                      // drain previous frag: 2 ex2-pairs/iter
                const int nf = it >> 1;
                if (it & 1) rs1[mf - 1] += ex2v(P[nf][2]) + ex2v(P[nf][3]);
                else        rs0[mf - 1] += ex2v(P[nf][0]) + ex2v(P[nf][1]);
            }
        }
    }
    // Drain last frag (mf = 3 lives in acc[1]).
    {
        float (*P)[4] = acc[1];
#pragma unroll
        for (int nf = 0; nf < 4; nf++) {
            rs0[3] += ex2v(P[nf][0]) + ex2v(P[nf][1]);
            rs1[3] += ex2v(P[nf][2]) + ex2v(P[nf][3]);
        }
    }

    const int g  = lane >> 2;
    const int t4 = lane & 3;
#pragma unroll
    for (int mf = 0; mf < 4; mf++) {
        rs0[mf] += __shfl_xor_sync(0xffffffffu, rs0[mf], 1);
        rs0[mf] += __shfl_xor_sync(0xffffffffu, rs0[mf], 2);
        rs1[mf] += __shfl_xor_sync(0xffffffffu, rs1[mf], 1);
        rs1[mf] += __shfl_xor_sync(0xffffffffu, rs1[mf], 2);
    }

    __syncthreads();                           // tiles no longer needed; reuse smem
    float* red = (float*)smem;                 // [128 rows][4 wn]
    if (t4 == 0) {
#pragma unroll
        for (int mf = 0; mf < 4; mf++) {
            int r0 = wm * 64 + mf * 16 + g;
            red[r0 * 4 + wn]       = rs0[mf];
            red[(r0 + 8) * 4 + wn] = rs1[mf];
        }
    }
    __syncthreads();
    if (tid < 128) {
        float s = (red[tid * 4 + 0] + red[tid * 4 + 1]) +
                  (red[tid * 4 + 2] + red[tid * 4 + 3]);
        g_partial[(size_t)bn * NN + bm * 128 + tid] = s;   // fixed order, no atomics
    }
}

// ---------------------------------------------------------------------------
// Kernel 3: per-row total over 128 column-block partials, loss, block sums.
// ---------------------------------------------------------------------------
__global__ void reduce_kernel() {
    int r = blockIdx.x * blockDim.x + threadIdx.x;
    float t = 0.f;
#pragma unroll 8
    for (int cb = 0; cb < NN / 128; cb++) t += g_partial[(size_t)cb * NN + r];
    float lr = logf(t + EPS_F) - g_pos[r];

    __shared__ float sm[256];
    sm[threadIdx.x] = lr;
    __syncthreads();
    for (int o = 128; o; o >>= 1) {
        if (threadIdx.x < o) sm[threadIdx.x] += sm[threadIdx.x + o];
        __syncthreads();
    }
    if (threadIdx.x == 0) g_blocksum[blockIdx.x] = sm[0];
}

__global__ void final_kernel(float* __restrict__ out) {
    __shared__ float sm[64];
    int t = threadIdx.x;
    sm[t] = g_blocksum[t];
    __syncthreads();
    for (int o = 32; o; o >>= 1) {
        if (t < o) sm[t] += sm[t + o];
        __syncthreads();
    }
    if (t == 0) out[0] = sm[0] * (1.0f / (float)NN);
}

// ---------------------------------------------------------------------------
extern "C" void kernel_launch(void* const* d_in, const int* in_sizes, int n_in,
                              void* d_out, int out_size) {
    const float* U = (const float*)d_in[0];
    const float* I = (const float*)d_in[1];
    float* out = (float*)d_out;

    const int SMEM_BYTES = 128 * SROWA + 128 * SROWBB;   // 49152
    cudaFuncSetAttribute(gemm_exp_kernel,
                         cudaFuncAttributeMaxDynamicSharedMemorySize, SMEM_BYTES);

    prep_kernel<<<NN / 8, 256>>>(U, I);

    dim3 grid(NN / 128, NN / 128);
    gemm_exp_kernel<<<grid, 256, SMEM_BYTES>>>();

    reduce_kernel<<<NN / 256, 256>>>();
    final_kernel<<<1, 64>>>(out);
}

// round 10
// speedup vs baseline: 1.7011x; 1.5099x over previous
#include <cuda_runtime.h>
#include <cuda_fp16.h>
#include <cstdint>

#define NN 16384
#define DD 64
#define KK 64            // plain fp16 GEMM: ah . wh (residual dropped; ~1e-5 rel err)
#define SROW 128         // smem row stride bytes (8 x 16B chunks) for both operands

constexpr float TAU_F   = 0.28f;
constexpr float EPS_F   = 1e-8f;
constexpr float LOG2E_F = 1.4426950408889634f;

// Scratch (allocation-free: __device__ globals)
__device__ __half g_a[NN * KK];               // A rows: fp16(u_n * log2e/TAU)
__device__ __half g_b[NN * KK];               // B rows: fp16(u_n + i_n)
__device__ float g_pos[NN];
__device__ float g_partial[(NN / 128) * NN];  // per-column-block partial row sums
__device__ float g_blocksum[64];

__device__ __forceinline__ uint32_t smem_u32(const void* p) {
    uint32_t a;
    asm("{ .reg .u64 t; cvta.to.shared.u64 t, %1; cvt.u32.u64 %0, t; }" : "=r"(a) : "l"(p));
    return a;
}
__device__ __forceinline__ void cp16(uint32_t saddr, const void* g) {
    asm volatile("cp.async.cg.shared.global [%0], [%1], 16;" :: "r"(saddr), "l"(g));
}
__device__ __forceinline__ void ldsm_x4(uint32_t* r, uint32_t addr) {
    asm volatile("ldmatrix.sync.aligned.m8n8.x4.shared.b16 {%0,%1,%2,%3}, [%4];"
                 : "=r"(r[0]), "=r"(r[1]), "=r"(r[2]), "=r"(r[3]) : "r"(addr));
}
__device__ __forceinline__ void mma16816(float* c, const uint32_t* a,
                                         uint32_t b0, uint32_t b1) {
    asm volatile(
        "mma.sync.aligned.m16n8k16.row.col.f32.f16.f16.f32 "
        "{%0,%1,%2,%3}, {%4,%5,%6,%7}, {%8,%9}, {%0,%1,%2,%3};"
        : "+f"(c[0]), "+f"(c[1]), "+f"(c[2]), "+f"(c[3])
        : "r"(a[0]), "r"(a[1]), "r"(a[2]), "r"(a[3]), "r"(b0), "r"(b1));
}
__device__ __forceinline__ float ex2v(float x) {
    float e;
    asm volatile("ex2.approx.ftz.f32 %0, %1;" : "=f"(e) : "f"(x));
    return e;
}

// ---------------------------------------------------------------------------
// Kernel 1: normalize, build fp16 A (scaled) and B (w = u_n + i_n).
// ---------------------------------------------------------------------------
__global__ void prep_kernel(const float* __restrict__ U, const float* __restrict__ I) {
    int row  = blockIdx.x * 8 + (threadIdx.x >> 5);
    int lane = threadIdx.x & 31;

    const float* up = U + (size_t)row * DD;
    const float* ip = I + (size_t)row * DD;
    float u0 = up[lane], u1 = up[lane + 32];
    float i0 = ip[lane], i1 = ip[lane + 32];

    float su = u0 * u0 + u1 * u1;
    float si = i0 * i0 + i1 * i1;
#pragma unroll
    for (int o = 16; o; o >>= 1) {
        su += __shfl_xor_sync(0xffffffffu, su, o);
        si += __shfl_xor_sync(0xffffffffu, si, o);
    }
    float inu = rsqrtf(fmaxf(su, 1e-24f));
    float ini = rsqrtf(fmaxf(si, 1e-24f));

    float un0 = u0 * inu, un1 = u1 * inu;
    float vn0 = i0 * ini, vn1 = i1 * ini;

    float d = un0 * vn0 + un1 * vn1;
#pragma unroll
    for (int o = 16; o; o >>= 1) d += __shfl_xor_sync(0xffffffffu, d, o);

    const float SC = LOG2E_F / TAU_F;   // GEMM output directly = log2 of each exp term
    size_t base = (size_t)row * KK;
    g_a[base + lane]      = __float2half_rn(un0 * SC);
    g_a[base + 32 + lane] = __float2half_rn(un1 * SC);
    g_b[base + lane]      = __float2half_rn(un0 + vn0);
    g_b[base + 32 + lane] = __float2half_rn(un1 + vn1);

    if (lane == 0) g_pos[row] = d * (1.0f / TAU_F);
}

// ---------------------------------------------------------------------------
// Kernel 2: fp16 mma.sync GEMM, 128x128 tile, K=64 resident in smem,
// ldmatrix fragment loads + ex2 + row-sum epilogue in registers.
// 8 warps 2(M) x 4(N); warp tile 64x32.
// Smem: rows = 8 x 16B chunks (128B); chunk swizzle c ^ (row & 7).
// ---------------------------------------------------------------------------
__global__ void __launch_bounds__(256, 2) gemm_exp_kernel() {
    extern __shared__ __align__(16) char smem[];
    const uint32_t sb = smem_u32(smem);
    const uint32_t sA = sb;                    // 16 KB
    const uint32_t sB = sb + 128 * SROW;       // 16 KB

    const int tid  = threadIdx.x;
    const int wid  = tid >> 5;
    const int lane = tid & 31;
    const int wm   = wid >> 2;                 // 0..1
    const int wn   = wid & 3;                  // 0..3
    const int bm = blockIdx.y, bn = blockIdx.x;

    const char* Ag = (const char*)g_a + (size_t)bm * 128 * (KK * 2);
    const char* Bg = (const char*)g_b + (size_t)bn * 128 * (KK * 2);

    // Load both tiles: 128 rows x 8 chunks(16B) each operand.
#pragma unroll
    for (int it = 0; it < 4; it++) {
        int idx = it * 256 + tid;              // 0..1023
        int row = idx >> 3;
        int c   = idx & 7;
        uint32_t sw = (uint32_t)(row * SROW + ((c ^ (row & 7)) << 4));
        size_t   go = (size_t)row * (KK * 2) + c * 16;
        cp16(sA + sw, Ag + go);
        cp16(sB + sw, Bg + go);
    }
    asm volatile("cp.async.commit_group;" ::: "memory");

    float acc[4][4][4];
#pragma unroll
    for (int i = 0; i < 4; i++)
#pragma unroll
        for (int j = 0; j < 4; j++)
#pragma unroll
            for (int r = 0; r < 4; r++) acc[i][j][r] = 0.f;

    asm volatile("cp.async.wait_group 0;" ::: "memory");
    __syncthreads();

    const int lr16 = lane & 15;                // ldmatrix row within 16
    const int lhi  = lane >> 4;                // k-chunk half select

#pragma unroll
    for (int ks = 0; ks < KK / 16; ks++) {     // 4 k-steps
        const int ch = 2 * ks + lhi;           // 16B chunk index (0..7)
        uint32_t a[4][4];
#pragma unroll
        for (int mf = 0; mf < 4; mf++) {
            int row = wm * 64 + mf * 16 + lr16;
            ldsm_x4(a[mf], sA + row * SROW + ((ch ^ (row & 7)) << 4));
        }
        uint32_t bfr[2][4];
#pragma unroll
        for (int p = 0; p < 2; p++) {
            int row = wn * 32 + p * 16 + lr16;
            ldsm_x4(bfr[p], sB + row * SROW + ((ch ^ (row & 7)) << 4));
        }
        // bfr[p] = {b0(nf=2p), b0(nf=2p+1), b1(nf=2p), b1(nf=2p+1)}
#pragma unroll
        for (int mf = 0; mf < 4; mf++) {
            mma16816(acc[mf][0], a[mf], bfr[0][0], bfr[0][2]);
            mma16816(acc[mf][1], a[mf], bfr[0][1], bfr[0][3]);
            mma16816(acc[mf][2], a[mf], bfr[1][0], bfr[1][2]);
            mma16816(acc[mf][3], a[mf], bfr[1][1], bfr[1][3]);
        }
    }

    // ---------------- Epilogue: exp2 + row sums (deterministic) ----------------
    const int g  = lane >> 2;                  // row-in-frag
    const int t4 = lane & 3;
    float rs0[4], rs1[4];
#pragma unroll
    for (int mf = 0; mf < 4; mf++) {
        float s0 = 0.f, s1 = 0.f;
#pragma unroll
        for (int nf = 0; nf < 4; nf++) {
            s0 += ex2v(acc[mf][nf][0]) + ex2v(acc[mf][nf][1]);
            s1 += ex2v(acc[mf][nf][2]) + ex2v(acc[mf][nf][3]);
        }
        rs0[mf] = s0; rs1[mf] = s1;
    }
#pragma unroll
    for (int mf = 0; mf < 4; mf++) {
        rs0[mf] += __shfl_xor_sync(0xffffffffu, rs0[mf], 1);
        rs0[mf] += __shfl_xor_sync(0xffffffffu, rs0[mf], 2);
        rs1[mf] += __shfl_xor_sync(0xffffffffu, rs1[mf], 1);
        rs1[mf] += __shfl_xor_sync(0xffffffffu, rs1[mf], 2);
    }

    __syncthreads();                           // tiles no longer needed; reuse smem
    float* red = (float*)smem;                 // [128 rows][4 wn]
    if (t4 == 0) {
#pragma unroll
        for (int mf = 0; mf < 4; mf++) {
            int r0 = wm * 64 + mf * 16 + g;
            red[r0 * 4 + wn]       = rs0[mf];
            red[(r0 + 8) * 4 + wn] = rs1[mf];
        }
    }
    __syncthreads();
    if (tid < 128) {
        float s = (red[tid * 4 + 0] + red[tid * 4 + 1]) +
                  (red[tid * 4 + 2] + red[tid * 4 + 3]);
        g_partial[(size_t)bn * NN + bm * 128 + tid] = s;   // fixed order, no atomics
    }
}

// ---------------------------------------------------------------------------
// Kernel 3: per-row total over 128 column-block partials, loss, block sums.
// ---------------------------------------------------------------------------
__global__ void reduce_kernel() {
    int r = blockIdx.x * blockDim.x + threadIdx.x;
    float t = 0.f;
#pragma unroll 8
    for (int cb = 0; cb < NN / 128; cb++) t += g_partial[(size_t)cb * NN + r];
    float lr = logf(t + EPS_F) - g_pos[r];

    __shared__ float sm[256];
    sm[threadIdx.x] = lr;
    __syncthreads();
    for (int o = 128; o; o >>= 1) {
        if (threadIdx.x < o) sm[threadIdx.x] += sm[threadIdx.x + o];
        __syncthreads();
    }
    if (threadIdx.x == 0) g_blocksum[blockIdx.x] = sm[0];
}

__global__ void final_kernel(float* __restrict__ out) {
    __shared__ float sm[64];
    int t = threadIdx.x;
    sm[t] = g_blocksum[t];
    __syncthreads();
    for (int o = 32; o; o >>= 1) {
        if (t < o) sm[t] += sm[t + o];
        __syncthreads();
    }
    if (t == 0) out[0] = sm[0] * (1.0f / (float)NN);
}

// ---------------------------------------------------------------------------
extern "C" void kernel_launch(void* const* d_in, const int* in_sizes, int n_in,
                              void* d_out, int out_size) {
    const float* U = (const float*)d_in[0];
    const float* I = (const float*)d_in[1];
    float* out = (float*)d_out;

    const int SMEM_BYTES = 2 * 128 * SROW;     // 32768
    cudaFuncSetAttribute(gemm_exp_kernel,
                         cudaFuncAttributeMaxDynamicSharedMemorySize, SMEM_BYTES);

    prep_kernel<<<NN / 8, 256>>>(U, I);

    dim3 grid(NN / 128, NN / 128);
    gemm_exp_kernel<<<grid, 256, SMEM_BYTES>>>();

    reduce_kernel<<<NN / 256, 256>>>();
    final_kernel<<<1, 64>>>(out);
}